// round 2
// baseline (speedup 1.0000x reference)
#include <cuda_runtime.h>
#include <cuda_bf16.h>

// remaining[i] = ! exists j: addr2site_map[j]==slice_sites[i] && sig[j]>0
// avail_scores[i] = remaining[i] ? scores[i] : 0
//
// addr2site_map is sorted -> lower_bound binary search + tiny duplicate scan.
// slice_sites is sorted -> adjacent threads probe adjacent map positions,
// so the binary search tree is warp-coherent and L1/L2 resident (24MB map
// fits in the 126MB L2).

__global__ __launch_bounds__(256)
void legalize_clb_kernel(const int* __restrict__ slice_sites,
                         const int* __restrict__ sig,
                         const int* __restrict__ addr2site,
                         const float* __restrict__ scores,
                         float* __restrict__ out_remaining,
                         float* __restrict__ out_scores,
                         int n_slice, int n_clb) {
    int i = blockIdx.x * blockDim.x + threadIdx.x;
    if (i >= n_slice) return;

    int s = __ldg(slice_sites + i);

    // lower_bound(addr2site, s)
    int lo = 0, hi = n_clb;
    while (lo < hi) {
        int mid = (lo + hi) >> 1;
        if (__ldg(addr2site + mid) < s) lo = mid + 1;
        else hi = mid;
    }

    // scan duplicate run: found iff any matching entry has sig > 0
    bool found = false;
    int j = lo;
    while (j < n_clb && __ldg(addr2site + j) == s) {
        if (__ldg(sig + j) > 0) { found = true; break; }
        ++j;
    }

    out_remaining[i] = found ? 0.0f : 1.0f;
    out_scores[i]    = found ? 0.0f : __ldg(scores + i);
}

// Fallback when out_size only holds one array: write remaining (first tuple elem).
__global__ __launch_bounds__(256)
void legalize_clb_kernel_single(const int* __restrict__ slice_sites,
                                const int* __restrict__ sig,
                                const int* __restrict__ addr2site,
                                const float* __restrict__ scores,
                                float* __restrict__ out_remaining,
                                int n_slice, int n_clb) {
    int i = blockIdx.x * blockDim.x + threadIdx.x;
    if (i >= n_slice) return;

    int s = __ldg(slice_sites + i);
    int lo = 0, hi = n_clb;
    while (lo < hi) {
        int mid = (lo + hi) >> 1;
        if (__ldg(addr2site + mid) < s) lo = mid + 1;
        else hi = mid;
    }
    bool found = false;
    int j = lo;
    while (j < n_clb && __ldg(addr2site + j) == s) {
        if (__ldg(sig + j) > 0) { found = true; break; }
        ++j;
    }
    out_remaining[i] = found ? 0.0f : 1.0f;
}

extern "C" void kernel_launch(void* const* d_in, const int* in_sizes, int n_in,
                              void* d_out, int out_size) {
    const int*   slice_sites = (const int*)  d_in[0];
    const int*   sig         = (const int*)  d_in[1];
    const int*   addr2site   = (const int*)  d_in[2];
    const float* scores      = (const float*)d_in[3];

    int n_slice = in_sizes[0];
    int n_clb   = in_sizes[1];

    float* out = (float*)d_out;

    int threads = 256;
    int blocks  = (n_slice + threads - 1) / threads;

    if (out_size >= 2 * n_slice) {
        legalize_clb_kernel<<<blocks, threads>>>(
            slice_sites, sig, addr2site, scores,
            out, out + n_slice, n_slice, n_clb);
    } else {
        legalize_clb_kernel_single<<<blocks, threads>>>(
            slice_sites, sig, addr2site, scores,
            out, n_slice, n_clb);
    }
}

// round 3
// speedup vs baseline: 2.6452x; 2.6452x over previous
#include <cuda_runtime.h>
#include <cuda_bf16.h>

// remaining[i] = ! exists j: addr2site_map[j]==slice_sites[i] && sig[j]>0
// avail_scores[i] = remaining[i] ? scores[i] : 0
//
// Site ids are in [0, 2048*4096). Represent the assigned set as a 1MB bitmap
// (L2-resident). Replaces the serial binary-search dependent-load chain
// (latency-bound, 150us) with three pure-streaming kernels.

#define NUM_SITES (2048 * 4096)           // 8,388,608
#define BITMAP_WORDS (NUM_SITES / 32)     // 262,144 -> 1 MB

__device__ unsigned int g_bitmap[BITMAP_WORDS];

__global__ __launch_bounds__(256)
void zero_bitmap_kernel() {
    int i = blockIdx.x * blockDim.x + threadIdx.x;
    // 262144 / 4 = 65536 uint4 stores
    if (i < BITMAP_WORDS / 4) {
        ((uint4*)g_bitmap)[i] = make_uint4(0u, 0u, 0u, 0u);
    }
}

__global__ __launch_bounds__(256)
void scatter_kernel(const int* __restrict__ sig,
                    const int* __restrict__ addr2site,
                    int n_clb) {
    int i = blockIdx.x * blockDim.x + threadIdx.x;
    if (i >= n_clb) return;
    int v = __ldg(sig + i);
    if (v > 0) {
        unsigned int site = (unsigned int)__ldg(addr2site + i);
        // sites guaranteed < NUM_SITES by problem construction
        atomicOr(&g_bitmap[site >> 5], 1u << (site & 31u));  // REDG (no return)
    }
}

__device__ __forceinline__ float2 probe(int site, const float score) {
    unsigned int w = __ldg((const unsigned int*)&g_bitmap[(unsigned)site >> 5]);
    bool found = (w >> ((unsigned)site & 31u)) & 1u;
    float rem = found ? 0.0f : 1.0f;
    return make_float2(rem, found ? 0.0f : score);
}

__global__ __launch_bounds__(256)
void gather_kernel(const int* __restrict__ slice_sites,
                   const float* __restrict__ scores,
                   float* __restrict__ out_remaining,
                   float* __restrict__ out_scores,
                   int n_slice) {
    int i = blockIdx.x * blockDim.x + threadIdx.x;   // vec4 index
    int n4 = n_slice >> 2;
    if (i < n4) {
        int4   s4 = __ldg((const int4*)slice_sites + i);
        float4 c4 = __ldg((const float4*)scores + i);
        float2 r0 = probe(s4.x, c4.x);
        float2 r1 = probe(s4.y, c4.y);
        float2 r2 = probe(s4.z, c4.z);
        float2 r3 = probe(s4.w, c4.w);
        ((float4*)out_remaining)[i] = make_float4(r0.x, r1.x, r2.x, r3.x);
        ((float4*)out_scores)[i]    = make_float4(r0.y, r1.y, r2.y, r3.y);
    }
    // tail (n_slice % 4) handled by first few threads
    int tail = n_slice & 3;
    if (i < tail) {
        int idx = (n4 << 2) + i;
        float2 r = probe(__ldg(slice_sites + idx), __ldg(scores + idx));
        out_remaining[idx] = r.x;
        out_scores[idx]    = r.y;
    }
}

__global__ __launch_bounds__(256)
void gather_kernel_single(const int* __restrict__ slice_sites,
                          const float* __restrict__ scores,
                          float* __restrict__ out_remaining,
                          int n_slice) {
    int i = blockIdx.x * blockDim.x + threadIdx.x;
    if (i >= n_slice) return;
    float2 r = probe(__ldg(slice_sites + i), __ldg(scores + i));
    out_remaining[i] = r.x;
}

extern "C" void kernel_launch(void* const* d_in, const int* in_sizes, int n_in,
                              void* d_out, int out_size) {
    const int*   slice_sites = (const int*)  d_in[0];
    const int*   sig         = (const int*)  d_in[1];
    const int*   addr2site   = (const int*)  d_in[2];
    const float* scores      = (const float*)d_in[3];

    int n_slice = in_sizes[0];
    int n_clb   = in_sizes[1];

    float* out = (float*)d_out;

    zero_bitmap_kernel<<<(BITMAP_WORDS / 4 + 255) / 256, 256>>>();
    scatter_kernel<<<(n_clb + 255) / 256, 256>>>(sig, addr2site, n_clb);

    if (out_size >= 2 * n_slice) {
        int n4 = (n_slice >> 2) + 4;  // cover vec body + tail threads
        gather_kernel<<<(n4 + 255) / 256, 256>>>(
            slice_sites, scores, out, out + n_slice, n_slice);
    } else {
        gather_kernel_single<<<(n_slice + 255) / 256, 256>>>(
            slice_sites, scores, out, n_slice);
    }
}

// round 4
// speedup vs baseline: 2.7079x; 1.0237x over previous
#include <cuda_runtime.h>
#include <cuda_bf16.h>

// remaining[i] = ! exists j: addr2site_map[j]==slice_sites[i] && sig[j]>0
// avail_scores[i] = remaining[i] ? scores[i] : 0
//
// Assigned-set as a 1MB L2-resident bitmap. R3: warp-aggregated atomics in
// scatter (sorted addr2site => ~16-way same-word conflicts otherwise) and
// 8-elem/thread gather for MLP.

#define NUM_SITES (2048 * 4096)           // 8,388,608
#define BITMAP_WORDS (NUM_SITES / 32)     // 262,144 -> 1 MB

__device__ unsigned int g_bitmap[BITMAP_WORDS];

__global__ __launch_bounds__(256)
void zero_bitmap_kernel() {
    int i = blockIdx.x * blockDim.x + threadIdx.x;
    if (i < BITMAP_WORDS / 4) {
        ((uint4*)g_bitmap)[i] = make_uint4(0u, 0u, 0u, 0u);
    }
}

__device__ __forceinline__ void agg_atomic_or(bool pred, unsigned int site,
                                              unsigned int lane) {
    // Warp-aggregated atomicOr: merge bits of lanes targeting the same word.
    unsigned int am = __ballot_sync(0xffffffffu, pred);
    if (pred) {
        unsigned int w = site >> 5;
        unsigned int b = 1u << (site & 31u);
        unsigned int grp = __match_any_sync(am, w);
        unsigned int orv = __reduce_or_sync(grp, b);
        if ((unsigned int)(__ffs(grp) - 1) == lane)
            atomicOr(&g_bitmap[w], orv);
    }
}

__global__ __launch_bounds__(256)
void scatter_kernel(const int* __restrict__ sig,
                    const int* __restrict__ addr2site,
                    int n4) {               // n_clb/4 (n_clb divisible by 4)
    int i = blockIdx.x * blockDim.x + threadIdx.x;
    unsigned int lane = threadIdx.x & 31u;
    bool valid = (i < n4);
    int idx = valid ? i : 0;
    int4 v4 = __ldg((const int4*)sig + idx);
    int4 s4 = __ldg((const int4*)addr2site + idx);
    agg_atomic_or(valid && v4.x > 0, (unsigned)s4.x, lane);
    agg_atomic_or(valid && v4.y > 0, (unsigned)s4.y, lane);
    agg_atomic_or(valid && v4.z > 0, (unsigned)s4.z, lane);
    agg_atomic_or(valid && v4.w > 0, (unsigned)s4.w, lane);
}

__device__ __forceinline__ float2 probe(int site, const float score) {
    unsigned int w = __ldg((const unsigned int*)&g_bitmap[(unsigned)site >> 5]);
    bool found = (w >> ((unsigned)site & 31u)) & 1u;
    return make_float2(found ? 0.0f : 1.0f, found ? 0.0f : score);
}

__global__ __launch_bounds__(256)
void gather_kernel(const int* __restrict__ slice_sites,
                   const float* __restrict__ scores,
                   float* __restrict__ out_remaining,
                   float* __restrict__ out_scores,
                   int n_slice) {
    int i = blockIdx.x * blockDim.x + threadIdx.x;   // 8-elem index
    int n8 = n_slice >> 3;
    if (i < n8) {
        int base4 = i * 2;
        int4   sa = __ldg((const int4*)slice_sites + base4);
        int4   sb = __ldg((const int4*)slice_sites + base4 + 1);
        float4 ca = __ldg((const float4*)scores + base4);
        float4 cb = __ldg((const float4*)scores + base4 + 1);
        float2 r0 = probe(sa.x, ca.x);
        float2 r1 = probe(sa.y, ca.y);
        float2 r2 = probe(sa.z, ca.z);
        float2 r3 = probe(sa.w, ca.w);
        float2 r4 = probe(sb.x, cb.x);
        float2 r5 = probe(sb.y, cb.y);
        float2 r6 = probe(sb.z, cb.z);
        float2 r7 = probe(sb.w, cb.w);
        ((float4*)out_remaining)[base4]     = make_float4(r0.x, r1.x, r2.x, r3.x);
        ((float4*)out_remaining)[base4 + 1] = make_float4(r4.x, r5.x, r6.x, r7.x);
        ((float4*)out_scores)[base4]        = make_float4(r0.y, r1.y, r2.y, r3.y);
        ((float4*)out_scores)[base4 + 1]    = make_float4(r4.y, r5.y, r6.y, r7.y);
    }
    // tail (n_slice % 8): first few threads handle scalars
    int tail = n_slice & 7;
    if (i < tail) {
        int idx = (n8 << 3) + i;
        float2 r = probe(__ldg(slice_sites + idx), __ldg(scores + idx));
        out_remaining[idx] = r.x;
        out_scores[idx]    = r.y;
    }
}

__global__ __launch_bounds__(256)
void gather_kernel_single(const int* __restrict__ slice_sites,
                          const float* __restrict__ scores,
                          float* __restrict__ out_remaining,
                          int n_slice) {
    int i = blockIdx.x * blockDim.x + threadIdx.x;
    if (i >= n_slice) return;
    float2 r = probe(__ldg(slice_sites + i), __ldg(scores + i));
    out_remaining[i] = r.x;
}

extern "C" void kernel_launch(void* const* d_in, const int* in_sizes, int n_in,
                              void* d_out, int out_size) {
    const int*   slice_sites = (const int*)  d_in[0];
    const int*   sig         = (const int*)  d_in[1];
    const int*   addr2site   = (const int*)  d_in[2];
    const float* scores      = (const float*)d_in[3];

    int n_slice = in_sizes[0];
    int n_clb   = in_sizes[1];

    float* out = (float*)d_out;

    zero_bitmap_kernel<<<(BITMAP_WORDS / 4 + 255) / 256, 256>>>();

    int n4 = n_clb >> 2;   // n_clb = 6,000,000 divisible by 4
    scatter_kernel<<<(n4 + 255) / 256, 256>>>(sig, addr2site, n4);

    if (out_size >= 2 * n_slice) {
        int n8 = (n_slice >> 3) + 8;  // cover vec body + tail threads
        gather_kernel<<<(n8 + 255) / 256, 256>>>(
            slice_sites, scores, out, out + n_slice, n_slice);
    } else {
        gather_kernel_single<<<(n_slice + 255) / 256, 256>>>(
            slice_sites, scores, out, n_slice);
    }
}

// round 5
// speedup vs baseline: 3.2935x; 1.2163x over previous
#include <cuda_runtime.h>
#include <cuda_bf16.h>

// remaining[i] = ! exists j: addr2site_map[j]==slice_sites[i] && sig[j]>0
// avail_scores[i] = remaining[i] ? scores[i] : 0
//
// Both slice_sites and addr2site_map are SORTED -> fused sorted-sorted merge:
// one streaming kernel, no bitmap, no atomics, no zero pass.
// Block = 2048 slice sites; covering addr2site segment (~2050 entries) staged
// in smem; per-thread merge over 8 elements.

#define TILE 2048
#define SEG_MAX 3072

// Warp-cooperative 32-ary search. upper=false: first idx with a[idx] >= key.
// upper=true: first idx with a[idx] > key. ~5 rounds for n=6M.
__device__ __forceinline__ int warp_search(const int* __restrict__ a, int n,
                                           int key, unsigned lane, bool upper) {
    int lo = 0, hi = n;
    while (hi > lo) {
        int range = hi - lo;
        int chunk = (range + 31) >> 5;
        int p = lo + (int)lane * chunk;
        bool pred = false;
        if (p < hi) {
            int v = __ldg(a + p);
            pred = upper ? (v <= key) : (v < key);
        }
        unsigned bal = __ballot_sync(0xffffffffu, pred);
        int c = __popc(bal);
        if (c == 0) { hi = lo; break; }          // answer == lo
        int nl = lo + (c - 1) * chunk + 1;
        int nh = lo + c * chunk;
        if (nh > hi) nh = hi;
        lo = nl; hi = nh;
    }
    return lo;
}

template <bool WRITE_SCORES>
__global__ __launch_bounds__(256)
void fused_merge_kernel(const int* __restrict__ ss, const int* __restrict__ sig,
                        const int* __restrict__ a2s, const float* __restrict__ sc,
                        float* __restrict__ outR, float* __restrict__ outS,
                        int n_slice, int n_clb) {
    __shared__ int s_sites[SEG_MAX];
    __shared__ unsigned char s_flag[SEG_MAX];
    __shared__ int sb[2];

    int blk0 = blockIdx.x * TILE;
    int blkn = min(TILE, n_slice - blk0);
    if (blkn <= 0) return;

    int wid = threadIdx.x >> 5;
    unsigned lane = threadIdx.x & 31u;

    // Find the covering addr2site segment [a0, a1) for this block's value range.
    if (wid == 0) {
        int key = __ldg(ss + blk0);
        int r = warp_search(a2s, n_clb, key, lane, false);
        if (lane == 0) sb[0] = r;
    } else if (wid == 1) {
        int key = __ldg(ss + blk0 + blkn - 1);
        int r = warp_search(a2s, n_clb, key, lane, true);
        if (lane == 0) sb[1] = r;
    }
    __syncthreads();

    int a0 = sb[0], a1 = sb[1];
    int seg = a1 - a0;
    bool use_smem = (seg <= SEG_MAX);

    if (use_smem) {
        for (int k = threadIdx.x; k < seg; k += 256) {
            s_sites[k] = __ldg(a2s + a0 + k);
            s_flag[k]  = (__ldg(sig + a0 + k) > 0) ? 1 : 0;
        }
    }
    __syncthreads();

    int t0 = blk0 + (int)threadIdx.x * 8;
    int nelem = min(8, blk0 + blkn - t0);
    if (nelem <= 0) return;

    if (use_smem && nelem == 8) {
        int4   va = __ldg((const int4*)(ss + t0));
        int4   vb = __ldg((const int4*)(ss + t0) + 1);
        float4 ca = __ldg((const float4*)(sc + t0));
        float4 cb = __ldg((const float4*)(sc + t0) + 1);
        int   v[8] = {va.x, va.y, va.z, va.w, vb.x, vb.y, vb.z, vb.w};
        float c[8] = {ca.x, ca.y, ca.z, ca.w, cb.x, cb.y, cb.z, cb.w};

        // binary search for first element, then merge-advance for the rest
        int lo = 0, hi = seg, key0 = v[0];
        while (lo < hi) {
            int mid = (lo + hi) >> 1;
            if (s_sites[mid] < key0) lo = mid + 1; else hi = mid;
        }
        int p = lo;
        float r[8], o[8];
        #pragma unroll
        for (int e = 0; e < 8; e++) {
            int s = v[e];
            while (p < seg && s_sites[p] < s) ++p;
            bool f = false;
            int q = p;
            while (q < seg && s_sites[q] == s) {
                if (s_flag[q]) { f = true; break; }
                ++q;
            }
            r[e] = f ? 0.0f : 1.0f;
            o[e] = f ? 0.0f : c[e];
        }
        ((float4*)(outR + t0))[0] = make_float4(r[0], r[1], r[2], r[3]);
        ((float4*)(outR + t0))[1] = make_float4(r[4], r[5], r[6], r[7]);
        if (WRITE_SCORES) {
            ((float4*)(outS + t0))[0] = make_float4(o[0], o[1], o[2], o[3]);
            ((float4*)(outS + t0))[1] = make_float4(o[4], o[5], o[6], o[7]);
        }
    } else {
        // scalar / global fallback (partial tail threads, or oversized segment)
        for (int e = 0; e < nelem; e++) {
            int idx = t0 + e;
            int s = __ldg(ss + idx);
            bool f = false;
            if (use_smem) {
                int lo = 0, hi = seg;
                while (lo < hi) {
                    int mid = (lo + hi) >> 1;
                    if (s_sites[mid] < s) lo = mid + 1; else hi = mid;
                }
                while (lo < seg && s_sites[lo] == s) {
                    if (s_flag[lo]) { f = true; break; }
                    ++lo;
                }
            } else {
                int lo = a0, hi = a1;
                while (lo < hi) {
                    int mid = (lo + hi) >> 1;
                    if (__ldg(a2s + mid) < s) lo = mid + 1; else hi = mid;
                }
                while (lo < a1 && __ldg(a2s + lo) == s) {
                    if (__ldg(sig + lo) > 0) { f = true; break; }
                    ++lo;
                }
            }
            outR[idx] = f ? 0.0f : 1.0f;
            if (WRITE_SCORES) outS[idx] = f ? 0.0f : __ldg(sc + idx);
        }
    }
}

extern "C" void kernel_launch(void* const* d_in, const int* in_sizes, int n_in,
                              void* d_out, int out_size) {
    const int*   slice_sites = (const int*)  d_in[0];
    const int*   sig         = (const int*)  d_in[1];
    const int*   addr2site   = (const int*)  d_in[2];
    const float* scores      = (const float*)d_in[3];

    int n_slice = in_sizes[0];
    int n_clb   = in_sizes[1];

    float* out = (float*)d_out;
    int blocks = (n_slice + TILE - 1) / TILE;

    if (out_size >= 2 * n_slice) {
        fused_merge_kernel<true><<<blocks, 256>>>(
            slice_sites, sig, addr2site, scores,
            out, out + n_slice, n_slice, n_clb);
    } else {
        fused_merge_kernel<false><<<blocks, 256>>>(
            slice_sites, sig, addr2site, scores,
            out, nullptr, n_slice, n_clb);
    }
}